// round 2
// baseline (speedup 1.0000x reference)
#include <cuda_runtime.h>

// ---------------- problem-size constants (max) ----------------
#define N_MAX 100000
#define E_MAX 1600000

// ---------------- scratch (device globals; no allocation allowed) ----------
__device__ float g_deg[N_MAX];            // degree, then dinv in-place
__device__ float g_y  [N_MAX * 64];       // dinv * (x @ W)
__device__ float g_acc[N_MAX * 64];       // scatter accumulator
__device__ float g_h  [N_MAX * 64];       // layer output (h1 then h2)
__device__ float g_t1 [N_MAX * 128];      // MLP hidden 1
__device__ float g_t2 [N_MAX * 64];       // MLP hidden 2

// ---------------- small kernels ----------------
__global__ void k_init(float* acc, float* deg, int N) {
    int i = blockIdx.x * blockDim.x + threadIdx.x;
    if (i < N * 64) acc[i] = 0.f;
    if (i < N) deg[i] = 2.0f;              // improved=True: A + 2I
}

__global__ void k_count(const int* __restrict__ dst, float* __restrict__ deg, int E) {
    int i = blockIdx.x * blockDim.x + threadIdx.x;
    if (i < E) atomicAdd(&deg[dst[i]], 1.0f);
}

__global__ void k_dinv(float* deg, int N) {
    int i = blockIdx.x * blockDim.x + threadIdx.x;
    if (i < N) deg[i] = rsqrtf(deg[i]);
}

// scatter: acc[dst] += y[src], 16 threads (float4 each) per edge
__global__ void k_scatter(const int* __restrict__ src, const int* __restrict__ dst,
                          const float* __restrict__ y, float* __restrict__ acc, int E) {
    int idx = blockIdx.x * blockDim.x + threadIdx.x;
    if (idx >= E * 16) return;
    int e = idx >> 4;
    int j = idx & 15;
    int s = src[e];
    int d = dst[e];
    float4 v = ((const float4*)(y + (size_t)s * 64))[j];
    float* a = acc + (size_t)d * 64 + 4 * j;
    atomicAdd(a + 0, v.x);
    atomicAdd(a + 1, v.y);
    atomicAdd(a + 2, v.z);
    atomicAdd(a + 3, v.w);
}

// h = relu(dinv*(acc + 2y) + b); also re-zero acc for next layer
__global__ void k_epilogue(const float* __restrict__ y, float* __restrict__ acc,
                           const float* __restrict__ dinv, const float* __restrict__ b,
                           float* __restrict__ h, int N) {
    int i = blockIdx.x * blockDim.x + threadIdx.x;
    if (i >= N * 64) return;
    int row = i >> 6;
    int c   = i & 63;
    float v = dinv[row] * (acc[i] + 2.0f * y[i]) + b[c];
    h[i]   = fmaxf(v, 0.0f);
    acc[i] = 0.0f;
}

// ---------------- tiled fp32 GEMM ----------------
// OUT[N,M] = post( scale?(dinv[row]) * (X[N,K] @ W[K,M]) + bias? ), relu?
// DUAL: X row = concat(X0 row [64], X1 row [64]) (K must be 128)
template<int K, int M, bool DUAL, bool PRESCALE, bool BIAS, bool RELU>
__global__ void k_gemm(const float* __restrict__ X0, const float* __restrict__ X1,
                       const float* __restrict__ W,  const float* __restrict__ bias,
                       const float* __restrict__ dinv, float* __restrict__ OUT, int N) {
    constexpr int CG   = M / 4;          // float4 column groups
    constexpr int RG   = 256 / CG;       // row groups
    constexpr int TILE = RG * 4;         // rows per tile
    constexpr int XSTR = K + 1;          // padded x row stride (bank-conflict free)

    extern __shared__ float sm[];
    float* Ws = sm;                      // K*M
    float* Xs = sm + K * M;              // TILE * XSTR

    for (int i = threadIdx.x; i < K * M; i += 256) Ws[i] = W[i];
    __syncthreads();

    const int cg = threadIdx.x % CG;
    const int rg = threadIdx.x / CG;
    const int numTiles = (N + TILE - 1) / TILE;

    for (int tile = blockIdx.x; tile < numTiles; tile += gridDim.x) {
        const int row0 = tile * TILE;
        // stage X tile
        for (int i = threadIdx.x; i < TILE * K; i += 256) {
            int r = i / K, c = i % K;
            int gr = row0 + r;
            float v = 0.f;
            if (gr < N) {
                if (!DUAL) v = X0[(size_t)gr * K + c];
                else       v = (c < 64) ? X0[(size_t)gr * 64 + c]
                                        : X1[(size_t)gr * 64 + (c - 64)];
            }
            Xs[r * XSTR + c] = v;
        }
        __syncthreads();

        float4 acc0 = make_float4(0, 0, 0, 0), acc1 = acc0, acc2 = acc0, acc3 = acc0;
        const float* xrow = Xs + (rg * 4) * XSTR;
        #pragma unroll 8
        for (int k = 0; k < K; ++k) {
            float4 w = *(const float4*)(Ws + k * M + 4 * cg);
            float x0 = xrow[0 * XSTR + k];
            float x1 = xrow[1 * XSTR + k];
            float x2 = xrow[2 * XSTR + k];
            float x3 = xrow[3 * XSTR + k];
            acc0.x += x0 * w.x; acc0.y += x0 * w.y; acc0.z += x0 * w.z; acc0.w += x0 * w.w;
            acc1.x += x1 * w.x; acc1.y += x1 * w.y; acc1.z += x1 * w.z; acc1.w += x1 * w.w;
            acc2.x += x2 * w.x; acc2.y += x2 * w.y; acc2.z += x2 * w.z; acc2.w += x2 * w.w;
            acc3.x += x3 * w.x; acc3.y += x3 * w.y; acc3.z += x3 * w.z; acc3.w += x3 * w.w;
        }

        float4 accs[4] = {acc0, acc1, acc2, acc3};
        #pragma unroll
        for (int j = 0; j < 4; ++j) {
            int gr = row0 + rg * 4 + j;
            if (gr >= N) continue;
            float4 v = accs[j];
            if (PRESCALE) {
                float s = dinv[gr];
                v.x *= s; v.y *= s; v.z *= s; v.w *= s;
            }
            if (BIAS) {
                float4 bb4 = *(const float4*)(bias + 4 * cg);
                v.x += bb4.x; v.y += bb4.y; v.z += bb4.z; v.w += bb4.w;
            }
            if (RELU) {
                v.x = fmaxf(v.x, 0.f); v.y = fmaxf(v.y, 0.f);
                v.z = fmaxf(v.z, 0.f); v.w = fmaxf(v.w, 0.f);
            }
            *(float4*)(OUT + (size_t)gr * M + 4 * cg) = v;
        }
        __syncthreads();
    }
}

// ---------------- JAX threefry2x32 (key = [0, 42]) ----------------
__device__ __forceinline__ unsigned rotl32(unsigned v, int r) {
    return (v << r) | (v >> (32 - r));
}

__device__ __forceinline__ uint2 threefry(unsigned c0, unsigned c1) {
    const unsigned k0 = 0u, k1 = 42u;
    const unsigned k2 = k0 ^ k1 ^ 0x1BD11BDAu;
    unsigned x0 = c0 + k0, x1 = c1 + k1;
#define TF_RND(r) { x0 += x1; x1 = rotl32(x1, r); x1 ^= x0; }
    TF_RND(13) TF_RND(15) TF_RND(26) TF_RND(6)
    x0 += k1; x1 += k2 + 1u;
    TF_RND(17) TF_RND(29) TF_RND(16) TF_RND(24)
    x0 += k2; x1 += k0 + 2u;
    TF_RND(13) TF_RND(15) TF_RND(26) TF_RND(6)
    x0 += k0; x1 += k1 + 3u;
    TF_RND(17) TF_RND(29) TF_RND(16) TF_RND(24)
    x0 += k1; x1 += k2 + 4u;
    TF_RND(13) TF_RND(15) TF_RND(26) TF_RND(6)
    x0 += k2; x1 += k0 + 5u;
#undef TF_RND
    return make_uint2(x0, x1);
}

// JAX partitionable threefry (jax_threefry_partitionable=True, the modern
// default): 32-bit random bits at flat index i are
//   (o0, o1) = threefry2x32(key, (hi32(i), lo32(i)));  bits = o0 ^ o1
__device__ __forceinline__ unsigned tf_bits_part(unsigned i) {
    uint2 o = threefry(0u, i);     // hi32(i) == 0 for i < 2^32
    return o.x ^ o.y;
}

__device__ __forceinline__ float bits_to_uniform(unsigned b) {
    // jax: bitcast((b>>9)|0x3f800000) - 1, then u*(1-1e-20)+1e-20 (f32: u+1e-20), max(1e-20, .)
    float f = __uint_as_float((b >> 9) | 0x3f800000u) - 1.0f;
    f = f + 1e-20f;
    return fmaxf(f, 1e-20f);
}

// ---------------- final: t2 @ Wo + bo -> sigmoid -> gumbel hard sample -----
__global__ void k_final(const float* __restrict__ t2, const float* __restrict__ Wo,
                        const float* __restrict__ bo, float* __restrict__ out, int N) {
    __shared__ float ws[64];
    if (threadIdx.x < 64) ws[threadIdx.x] = Wo[threadIdx.x];
    __syncthreads();

    int warp = (blockIdx.x * blockDim.x + threadIdx.x) >> 5;
    int lane = threadIdx.x & 31;
    if (warp >= N) return;

    const float* row = t2 + (size_t)warp * 64;
    float s = row[lane] * ws[lane] + row[lane + 32] * ws[lane + 32];
    #pragma unroll
    for (int o = 16; o; o >>= 1) s += __shfl_xor_sync(0xffffffffu, s, o);

    float p = 1.0f / (1.0f + expf(-(s + bo[0])));

    // gumbel noise for (row,0) and (row,1): flat index into (N,2) = 2*row + col
    float g = 0.0f;
    if (lane < 2) {
        unsigned f = 2u * (unsigned)warp + (unsigned)lane;
        float u = bits_to_uniform(tf_bits_part(f));
        g = -logf(-logf(u));
    }
    float g0 = __shfl_sync(0xffffffffu, g, 0);
    float g1 = __shfl_sync(0xffffffffu, g, 1);

    if (lane == 0) {
        out[warp]     = p;                                        // prob
        out[N + warp] = ((p + g1) > ((1.0f - p) + g0)) ? 1.0f : 0.0f;  // ind (argmax, tie->0)
    }
}

// ---------------- launch ----------------
extern "C" void kernel_launch(void* const* d_in, const int* in_sizes, int n_in,
                              void* d_out, int out_size) {
    const float* rep = (const float*)d_in[0];
    const int*   ei  = (const int*)  d_in[1];
    const float* W1  = (const float*)d_in[2];
    const float* b1  = (const float*)d_in[3];
    const float* W2  = (const float*)d_in[4];
    const float* b2  = (const float*)d_in[5];
    const float* Wa  = (const float*)d_in[6];
    const float* ba  = (const float*)d_in[7];
    const float* Wb  = (const float*)d_in[8];
    const float* bb  = (const float*)d_in[9];
    const float* Wo  = (const float*)d_in[10];
    const float* bo  = (const float*)d_in[11];
    float* out = (float*)d_out;

    int N = in_sizes[0] / 64;
    int E = in_sizes[1] / 2;
    if (N > N_MAX || E > E_MAX) return;
    const int* src = ei;
    const int* dst = ei + E;

    float *deg, *y, *acc, *h, *t1, *t2;
    cudaGetSymbolAddress((void**)&deg, g_deg);
    cudaGetSymbolAddress((void**)&y,   g_y);
    cudaGetSymbolAddress((void**)&acc, g_acc);
    cudaGetSymbolAddress((void**)&h,   g_h);
    cudaGetSymbolAddress((void**)&t1,  g_t1);
    cudaGetSymbolAddress((void**)&t2,  g_t2);

    // smem sizes
    const int SM_G64  = (64 * 64   + 64 * 65)  * 4;   // ~33 KB
    const int SM_MLP1 = (128 * 128 + 32 * 129) * 4;   // ~80 KB
    const int SM_MLP2 = (128 * 64  + 64 * 129) * 4;   // ~64 KB
    cudaFuncSetAttribute((const void*)k_gemm<128,128,true ,false,true ,true >,
                         cudaFuncAttributeMaxDynamicSharedMemorySize, SM_MLP1);
    cudaFuncSetAttribute((const void*)k_gemm<128,64 ,false,false,true ,true >,
                         cudaFuncAttributeMaxDynamicSharedMemorySize, SM_MLP2);

    const int TB = 256;
    int gInit = (N * 64 + TB - 1) / TB;
    int gEdge = (E + TB - 1) / TB;
    int gN    = (N + TB - 1) / TB;
    int gScat = (E * 16 + TB - 1) / TB;
    int gElem = (N * 64 + TB - 1) / TB;

    // degree / dinv (acc zeroed here too)
    k_init <<<gInit, TB>>>(acc, deg, N);
    k_count<<<gEdge, TB>>>(dst, deg, E);
    k_dinv <<<gN,    TB>>>(deg, N);

    int tiles64 = (N + 63) / 64;
    int grid64  = tiles64 < 1480 ? tiles64 : 1480;

    // GCN layer 1:  y = dinv*(rep@W1); acc = scatter(y); h1 = relu(dinv*(acc+2y)+b1)
    k_gemm<64,64,false,true,false,false><<<grid64, TB, SM_G64>>>(rep, nullptr, W1, nullptr, deg, y, N);
    k_scatter <<<gScat, TB>>>(src, dst, y, acc, E);
    k_epilogue<<<gElem, TB>>>(y, acc, deg, b1, h, N);

    // GCN layer 2
    k_gemm<64,64,false,true,false,false><<<grid64, TB, SM_G64>>>(h, nullptr, W2, nullptr, deg, y, N);
    k_scatter <<<gScat, TB>>>(src, dst, y, acc, E);
    k_epilogue<<<gElem, TB>>>(y, acc, deg, b2, h, N);

    // MLP head: z = [rep, h2]
    k_gemm<128,128,true ,false,true,true><<<296, TB, SM_MLP1>>>(rep, h, Wa, ba, nullptr, t1, N);
    k_gemm<128,64 ,false,false,true,true><<<444, TB, SM_MLP2>>>(t1, nullptr, Wb, bb, nullptr, t2, N);

    // final projection + sigmoid + gumbel straight-through
    int gFin = (N + 7) / 8;   // 8 warps (rows) per block
    k_final<<<gFin, TB>>>(t2, Wo, bo, out, N);
}

// round 3
// speedup vs baseline: 2.7567x; 2.7567x over previous
#include <cuda_runtime.h>

// ---------------- problem-size constants (max) ----------------
#define N_MAX 100000
#define E_MAX 1600000

// ---------------- scratch (device globals; no allocation allowed) ----------
__device__ float g_deg [N_MAX];            // dinv
__device__ float g_y   [N_MAX * 64];       // dinv * (x @ W)
__device__ float g_h   [N_MAX * 64];       // layer output (h1 then h2)
__device__ float g_t1  [N_MAX * 128];      // MLP hidden 1
__device__ float g_t2  [N_MAX * 64];       // MLP hidden 2
__device__ int   g_cnt [N_MAX];            // dst histogram
__device__ int   g_rp  [N_MAX + 1];        // CSR row pointers (by dst)
__device__ int   g_wp  [N_MAX];            // fill write pointers
__device__ int   g_eidx[E_MAX];            // src ids grouped by dst
__device__ int   g_bsum[256];              // scan block partials

// ---------------- CSR build ----------------
__global__ void k_zero(int* cnt, int N) {
    int i = blockIdx.x * blockDim.x + threadIdx.x;
    if (i < N) cnt[i] = 0;
}

__global__ void k_hist(const int* __restrict__ dst, int* __restrict__ cnt, int E) {
    int i = blockIdx.x * blockDim.x + threadIdx.x;
    if (i < E) atomicAdd(&cnt[dst[i]], 1);
}

// block b scans 1024 elements (256 threads x 4); writes local-exclusive prefix
// into rp and the block total into bsum[b]
__global__ void k_scan1(const int* __restrict__ cnt, int* __restrict__ rp,
                        int* __restrict__ bsum, int N) {
    __shared__ int wsum[8];
    __shared__ int btot;
    int t = threadIdx.x, lane = t & 31, w = t >> 5;
    int base = blockIdx.x * 1024 + t * 4;
    int v0 = (base + 0 < N) ? cnt[base + 0] : 0;
    int v1 = (base + 1 < N) ? cnt[base + 1] : 0;
    int v2 = (base + 2 < N) ? cnt[base + 2] : 0;
    int v3 = (base + 3 < N) ? cnt[base + 3] : 0;
    int s = v0 + v1 + v2 + v3;
    int x = s;
    #pragma unroll
    for (int o = 1; o < 32; o <<= 1) {
        int y = __shfl_up_sync(0xffffffffu, x, o);
        if (lane >= o) x += y;
    }
    if (lane == 31) wsum[w] = x;
    __syncthreads();
    if (t == 0) {
        int a = 0;
        #pragma unroll
        for (int i = 0; i < 8; ++i) { int tmp = wsum[i]; wsum[i] = a; a += tmp; }
        btot = a;
    }
    __syncthreads();
    int off = (x - s) + wsum[w];          // exclusive offset within block
    if (base + 0 < N) rp[base + 0] = off;
    if (base + 1 < N) rp[base + 1] = off + v0;
    if (base + 2 < N) rp[base + 2] = off + v0 + v1;
    if (base + 3 < N) rp[base + 3] = off + v0 + v1 + v2;
    if (t == 0) bsum[blockIdx.x] = btot;
}

__global__ void k_scan2(int* bsum, int nB) {
    if (threadIdx.x == 0 && blockIdx.x == 0) {
        int a = 0;
        for (int i = 0; i < nB; ++i) { int t = bsum[i]; bsum[i] = a; a += t; }
    }
}

// finalize rowptr, reset write pointers, compute dinv = rsqrt(cnt + 2)
__global__ void k_scan3(const int* __restrict__ cnt, int* __restrict__ rp,
                        int* __restrict__ wp, float* __restrict__ dinv,
                        const int* __restrict__ bsum, int N, int E) {
    int i = blockIdx.x * blockDim.x + threadIdx.x;
    if (i < N) {
        int v = rp[i] + bsum[i >> 10];
        rp[i] = v;
        wp[i] = v;
        dinv[i] = rsqrtf((float)cnt[i] + 2.0f);
    }
    if (i == 0) rp[N] = E;
}

__global__ void k_fill(const int* __restrict__ src, const int* __restrict__ dst,
                       int* __restrict__ wp, int* __restrict__ eidx, int E) {
    int i = blockIdx.x * blockDim.x + threadIdx.x;
    if (i < E) {
        int pos = atomicAdd(&wp[dst[i]], 1);
        eidx[pos] = src[i];
    }
}

// ---------------- fused gather + epilogue ----------------
// one warp per dst node: h[i] = relu(dinv[i] * (sum_{s in nbrs(i)} y[s] + 2*y[i]) + b)
__global__ void k_gather(const float* __restrict__ y, const int* __restrict__ rp,
                         const int* __restrict__ eidx, const float* __restrict__ dinv,
                         const float* __restrict__ b, float* __restrict__ h, int N) {
    int warp = (blockIdx.x * blockDim.x + threadIdx.x) >> 5;
    int lane = threadIdx.x & 31;
    if (warp >= N) return;
    const int c = lane * 2;
    int beg = rp[warp], end = rp[warp + 1];

    float2 a0 = *(const float2*)(y + (size_t)warp * 64 + c);
    a0.x *= 2.0f; a0.y *= 2.0f;
    float2 a1 = make_float2(0.f, 0.f);

    for (int j0 = beg; j0 < end; j0 += 32) {
        int myj = j0 + lane;
        int sreg = (myj < end) ? eidx[myj] : 0;
        int n = min(32, end - j0);
        int t = 0;
        for (; t + 1 < n; t += 2) {
            int s0 = __shfl_sync(0xffffffffu, sreg, t);
            int s1 = __shfl_sync(0xffffffffu, sreg, t + 1);
            float2 v0 = *(const float2*)(y + (size_t)s0 * 64 + c);
            float2 v1 = *(const float2*)(y + (size_t)s1 * 64 + c);
            a0.x += v0.x; a0.y += v0.y;
            a1.x += v1.x; a1.y += v1.y;
        }
        if (t < n) {
            int s0 = __shfl_sync(0xffffffffu, sreg, t);
            float2 v0 = *(const float2*)(y + (size_t)s0 * 64 + c);
            a0.x += v0.x; a0.y += v0.y;
        }
    }
    float d = dinv[warp];
    float2 o;
    o.x = fmaxf(d * (a0.x + a1.x) + b[c],     0.0f);
    o.y = fmaxf(d * (a0.y + a1.y) + b[c + 1], 0.0f);
    *(float2*)(h + (size_t)warp * 64 + c) = o;
}

// ---------------- tiled fp32 GEMM ----------------
// OUT[N,M] = post( scale?(dinv[row]) * (X[N,K] @ W[K,M]) + bias? ), relu?
// DUAL: X row = concat(X0 row [64], X1 row [64]) (K must be 128)
template<int K, int M, bool DUAL, bool PRESCALE, bool BIAS, bool RELU>
__global__ void k_gemm(const float* __restrict__ X0, const float* __restrict__ X1,
                       const float* __restrict__ W,  const float* __restrict__ bias,
                       const float* __restrict__ dinv, float* __restrict__ OUT, int N) {
    constexpr int CG   = M / 4;          // float4 column groups
    constexpr int RG   = 256 / CG;       // row groups
    constexpr int TILE = RG * 4;         // rows per tile
    constexpr int XSTR = K + 1;          // padded x row stride

    extern __shared__ float sm[];
    float* Ws = sm;                      // K*M
    float* Xs = sm + K * M;              // TILE * XSTR

    for (int i = threadIdx.x; i < K * M; i += 256) Ws[i] = W[i];
    __syncthreads();

    const int cg = threadIdx.x % CG;
    const int rg = threadIdx.x / CG;
    const int numTiles = (N + TILE - 1) / TILE;

    for (int tile = blockIdx.x; tile < numTiles; tile += gridDim.x) {
        const int row0 = tile * TILE;
        for (int i = threadIdx.x; i < TILE * K; i += 256) {
            int r = i / K, c = i % K;
            int gr = row0 + r;
            float v = 0.f;
            if (gr < N) {
                if (!DUAL) v = X0[(size_t)gr * K + c];
                else       v = (c < 64) ? X0[(size_t)gr * 64 + c]
                                        : X1[(size_t)gr * 64 + (c - 64)];
            }
            Xs[r * XSTR + c] = v;
        }
        __syncthreads();

        float4 acc0 = make_float4(0, 0, 0, 0), acc1 = acc0, acc2 = acc0, acc3 = acc0;
        const float* xrow = Xs + (rg * 4) * XSTR;
        #pragma unroll 8
        for (int k = 0; k < K; ++k) {
            float4 w = *(const float4*)(Ws + k * M + 4 * cg);
            float x0 = xrow[0 * XSTR + k];
            float x1 = xrow[1 * XSTR + k];
            float x2 = xrow[2 * XSTR + k];
            float x3 = xrow[3 * XSTR + k];
            acc0.x += x0 * w.x; acc0.y += x0 * w.y; acc0.z += x0 * w.z; acc0.w += x0 * w.w;
            acc1.x += x1 * w.x; acc1.y += x1 * w.y; acc1.z += x1 * w.z; acc1.w += x1 * w.w;
            acc2.x += x2 * w.x; acc2.y += x2 * w.y; acc2.z += x2 * w.z; acc2.w += x2 * w.w;
            acc3.x += x3 * w.x; acc3.y += x3 * w.y; acc3.z += x3 * w.z; acc3.w += x3 * w.w;
        }

        float4 accs[4] = {acc0, acc1, acc2, acc3};
        #pragma unroll
        for (int j = 0; j < 4; ++j) {
            int gr = row0 + rg * 4 + j;
            if (gr >= N) continue;
            float4 v = accs[j];
            if (PRESCALE) {
                float s = dinv[gr];
                v.x *= s; v.y *= s; v.z *= s; v.w *= s;
            }
            if (BIAS) {
                float4 bb4 = *(const float4*)(bias + 4 * cg);
                v.x += bb4.x; v.y += bb4.y; v.z += bb4.z; v.w += bb4.w;
            }
            if (RELU) {
                v.x = fmaxf(v.x, 0.f); v.y = fmaxf(v.y, 0.f);
                v.z = fmaxf(v.z, 0.f); v.w = fmaxf(v.w, 0.f);
            }
            *(float4*)(OUT + (size_t)gr * M + 4 * cg) = v;
        }
        __syncthreads();
    }
}

// ---------------- JAX partitionable threefry2x32 (key = [0, 42]) ----------
__device__ __forceinline__ unsigned rotl32(unsigned v, int r) {
    return (v << r) | (v >> (32 - r));
}

__device__ __forceinline__ uint2 threefry(unsigned c0, unsigned c1) {
    const unsigned k0 = 0u, k1 = 42u;
    const unsigned k2 = k0 ^ k1 ^ 0x1BD11BDAu;
    unsigned x0 = c0 + k0, x1 = c1 + k1;
#define TF_RND(r) { x0 += x1; x1 = rotl32(x1, r); x1 ^= x0; }
    TF_RND(13) TF_RND(15) TF_RND(26) TF_RND(6)
    x0 += k1; x1 += k2 + 1u;
    TF_RND(17) TF_RND(29) TF_RND(16) TF_RND(24)
    x0 += k2; x1 += k0 + 2u;
    TF_RND(13) TF_RND(15) TF_RND(26) TF_RND(6)
    x0 += k0; x1 += k1 + 3u;
    TF_RND(17) TF_RND(29) TF_RND(16) TF_RND(24)
    x0 += k1; x1 += k2 + 4u;
    TF_RND(13) TF_RND(15) TF_RND(26) TF_RND(6)
    x0 += k2; x1 += k0 + 5u;
#undef TF_RND
    return make_uint2(x0, x1);
}

__device__ __forceinline__ unsigned tf_bits_part(unsigned i) {
    uint2 o = threefry(0u, i);
    return o.x ^ o.y;
}

__device__ __forceinline__ float bits_to_uniform(unsigned b) {
    float f = __uint_as_float((b >> 9) | 0x3f800000u) - 1.0f;
    f = f + 1e-20f;
    return fmaxf(f, 1e-20f);
}

// ---------------- final: t2 @ Wo + bo -> sigmoid -> gumbel hard sample -----
__global__ void k_final(const float* __restrict__ t2, const float* __restrict__ Wo,
                        const float* __restrict__ bo, float* __restrict__ out, int N) {
    __shared__ float ws[64];
    if (threadIdx.x < 64) ws[threadIdx.x] = Wo[threadIdx.x];
    __syncthreads();

    int warp = (blockIdx.x * blockDim.x + threadIdx.x) >> 5;
    int lane = threadIdx.x & 31;
    if (warp >= N) return;

    const float* row = t2 + (size_t)warp * 64;
    float s = row[lane] * ws[lane] + row[lane + 32] * ws[lane + 32];
    #pragma unroll
    for (int o = 16; o; o >>= 1) s += __shfl_xor_sync(0xffffffffu, s, o);

    float p = 1.0f / (1.0f + expf(-(s + bo[0])));

    float g = 0.0f;
    if (lane < 2) {
        unsigned f = 2u * (unsigned)warp + (unsigned)lane;
        float u = bits_to_uniform(tf_bits_part(f));
        g = -logf(-logf(u));
    }
    float g0 = __shfl_sync(0xffffffffu, g, 0);
    float g1 = __shfl_sync(0xffffffffu, g, 1);

    if (lane == 0) {
        out[warp]     = p;
        out[N + warp] = ((p + g1) > ((1.0f - p) + g0)) ? 1.0f : 0.0f;
    }
}

// ---------------- launch ----------------
extern "C" void kernel_launch(void* const* d_in, const int* in_sizes, int n_in,
                              void* d_out, int out_size) {
    const float* rep = (const float*)d_in[0];
    const int*   ei  = (const int*)  d_in[1];
    const float* W1  = (const float*)d_in[2];
    const float* b1  = (const float*)d_in[3];
    const float* W2  = (const float*)d_in[4];
    const float* b2  = (const float*)d_in[5];
    const float* Wa  = (const float*)d_in[6];
    const float* ba  = (const float*)d_in[7];
    const float* Wb  = (const float*)d_in[8];
    const float* bb  = (const float*)d_in[9];
    const float* Wo  = (const float*)d_in[10];
    const float* bo  = (const float*)d_in[11];
    float* out = (float*)d_out;

    int N = in_sizes[0] / 64;
    int E = in_sizes[1] / 2;
    if (N > N_MAX || E > E_MAX) return;
    const int* src = ei;
    const int* dst = ei + E;

    float *dinv, *y, *h, *t1, *t2;
    int *cnt, *rp, *wp, *eidx, *bsum;
    cudaGetSymbolAddress((void**)&dinv, g_deg);
    cudaGetSymbolAddress((void**)&y,    g_y);
    cudaGetSymbolAddress((void**)&h,    g_h);
    cudaGetSymbolAddress((void**)&t1,   g_t1);
    cudaGetSymbolAddress((void**)&t2,   g_t2);
    cudaGetSymbolAddress((void**)&cnt,  g_cnt);
    cudaGetSymbolAddress((void**)&rp,   g_rp);
    cudaGetSymbolAddress((void**)&wp,   g_wp);
    cudaGetSymbolAddress((void**)&eidx, g_eidx);
    cudaGetSymbolAddress((void**)&bsum, g_bsum);

    const int SM_G64  = (64 * 64   + 64 * 65)  * 4;
    const int SM_MLP1 = (128 * 128 + 32 * 129) * 4;
    const int SM_MLP2 = (128 * 64  + 64 * 129) * 4;
    cudaFuncSetAttribute((const void*)k_gemm<128,128,true ,false,true ,true >,
                         cudaFuncAttributeMaxDynamicSharedMemorySize, SM_MLP1);
    cudaFuncSetAttribute((const void*)k_gemm<128,64 ,false,false,true ,true >,
                         cudaFuncAttributeMaxDynamicSharedMemorySize, SM_MLP2);

    const int TB = 256;
    int gN    = (N + TB - 1) / TB;
    int gEdge = (E + TB - 1) / TB;
    int nB    = (N + 1023) / 1024;
    int gWarp = (N * 32 + TB - 1) / TB;

    // ---- CSR build (also yields exact degree -> dinv) ----
    k_zero <<<gN,    TB>>>(cnt, N);
    k_hist <<<gEdge, TB>>>(dst, cnt, E);
    k_scan1<<<nB,    256>>>(cnt, rp, bsum, N);
    k_scan2<<<1,     32>>>(bsum, nB);
    k_scan3<<<gN,    TB>>>(cnt, rp, wp, dinv, bsum, N, E);
    k_fill <<<gEdge, TB>>>(src, dst, wp, eidx, E);

    int tiles64 = (N + 63) / 64;
    int grid64  = tiles64 < 1480 ? tiles64 : 1480;

    // ---- GCN layer 1 ----
    k_gemm<64,64,false,true,false,false><<<grid64, TB, SM_G64>>>(rep, nullptr, W1, nullptr, dinv, y, N);
    k_gather<<<gWarp, TB>>>(y, rp, eidx, dinv, b1, h, N);

    // ---- GCN layer 2 ----
    k_gemm<64,64,false,true,false,false><<<grid64, TB, SM_G64>>>(h, nullptr, W2, nullptr, dinv, y, N);
    k_gather<<<gWarp, TB>>>(y, rp, eidx, dinv, b2, h, N);

    // ---- MLP head: z = [rep, h2] ----
    k_gemm<128,128,true ,false,true,true><<<296, TB, SM_MLP1>>>(rep, h, Wa, ba, nullptr, t1, N);
    k_gemm<128,64 ,false,false,true,true><<<444, TB, SM_MLP2>>>(t1, nullptr, Wb, bb, nullptr, t2, N);

    // ---- final projection + sigmoid + gumbel straight-through ----
    int gFin = (N + 7) / 8;
    k_final<<<gFin, TB>>>(t2, Wo, bo, out, N);
}